// round 2
// baseline (speedup 1.0000x reference)
#include <cuda_runtime.h>
#include <math.h>
#include <stdint.h>

#define NW 8192
#define LC 16
#define CD 100
#define WD 300
#define HD 512
#define HH 256
#define G4 1024
#define T1 48
#define T2 32
#define KC (HH + CD)   // 356
#define KW (WD + HD)   // 812

// ---- scratch (device globals; no allocation allowed) ----
__device__ float g_gates[2][NW][G4];   // char gate preacts (per step, no bias)
__device__ float g_ch[2][NW][HH];      // char h (becomes char_feat)
__device__ float g_cc[2][NW][HH];      // char c
__device__ float g_wxg[2][NW][G4];     // word-level input gates (+biases)
__device__ float g_hs[2][NW][HH];      // word-level hidden states per step

__device__ __forceinline__ float sigf(float x)  { return 1.0f / (1.0f + __expf(-x)); }
__device__ __forceinline__ float tanhf_(float x){ return 2.0f / (1.0f + __expf(-2.0f * x)) - 1.0f; }

__device__ __forceinline__ uint32_t smem_u32(const void* p) {
    return (uint32_t)__cvta_generic_to_shared(p);
}

// ============================================================
// Char-level step GEMM: gates[dir][w][n] = sum_k A[w,k]*B[n,k]
// A = [h(256) | char_emb(100)], B = [Whh | Wih] (both K-major rows)
// 128x128 tile, BK=8, 256 threads, 8x8 per thread.
// ============================================================
__global__ void __launch_bounds__(256, 2)
char_gemm(const float* __restrict__ whh_f, const float* __restrict__ wih_f,
          const float* __restrict__ whh_b, const float* __restrict__ wih_b,
          const int*   __restrict__ cseq,  const float* __restrict__ cemb,
          int t)
{
    const int dir = blockIdx.z;
    const float* __restrict__ Whh = dir ? whh_b : whh_f;
    const float* __restrict__ Wih = dir ? wih_b : wih_f;
    const int tt   = dir ? (LC - 1 - t) : t;
    const int row0 = blockIdx.y * 128;
    const int col0 = blockIdx.x * 128;

    __shared__ float As[8][128];
    __shared__ float Bs[8][128];
    __shared__ int   sidx[128];

    const int tid = threadIdx.x;
    if (tid < 128) sidx[tid] = cseq[(row0 + tid) * LC + tt];

    const int tx = tid & 15;          // 0..15 -> col groups
    const int ty = tid >> 4;          // 0..15 -> row groups
    const int lrow = tid >> 1;        // 0..127 (load row)
    const int lkq  = (tid & 1) * 4;   // 0 or 4 (load k quad)

    float acc[8][8];
    #pragma unroll
    for (int i = 0; i < 8; i++)
        #pragma unroll
        for (int j = 0; j < 8; j++) acc[i][j] = 0.0f;

    const int kt0 = (t == 0) ? 32 : 0;   // at t=0, h==0 -> skip K[0,256)
    __syncthreads();

    for (int kt = kt0; kt < 45; kt++) {
        const int k = kt * 8 + lkq;      // quad base, multiple of 4

        float4 av = make_float4(0.f, 0.f, 0.f, 0.f);
        float4 bv = make_float4(0.f, 0.f, 0.f, 0.f);
        if (k < HH) {
            av = *reinterpret_cast<const float4*>(&g_ch[dir][row0 + lrow][k]);
            bv = *reinterpret_cast<const float4*>(&Whh[(col0 + lrow) * HH + k]);
        } else if (k < KC) {
            av = *reinterpret_cast<const float4*>(&cemb[sidx[lrow] * CD + (k - HH)]);
            bv = *reinterpret_cast<const float4*>(&Wih[(col0 + lrow) * CD + (k - HH)]);
        }
        __syncthreads();   // previous tile fully consumed
        As[lkq + 0][lrow] = av.x; As[lkq + 1][lrow] = av.y;
        As[lkq + 2][lrow] = av.z; As[lkq + 3][lrow] = av.w;
        Bs[lkq + 0][lrow] = bv.x; Bs[lkq + 1][lrow] = bv.y;
        Bs[lkq + 2][lrow] = bv.z; Bs[lkq + 3][lrow] = bv.w;
        __syncthreads();   // tile ready

        #pragma unroll
        for (int kk = 0; kk < 8; kk++) {
            const float4 a0 = *reinterpret_cast<const float4*>(&As[kk][ty * 4]);
            const float4 a1 = *reinterpret_cast<const float4*>(&As[kk][ty * 4 + 64]);
            const float4 b0 = *reinterpret_cast<const float4*>(&Bs[kk][tx * 4]);
            const float4 b1 = *reinterpret_cast<const float4*>(&Bs[kk][tx * 4 + 64]);
            const float ar[8] = {a0.x, a0.y, a0.z, a0.w, a1.x, a1.y, a1.z, a1.w};
            const float br[8] = {b0.x, b0.y, b0.z, b0.w, b1.x, b1.y, b1.z, b1.w};
            #pragma unroll
            for (int i = 0; i < 8; i++)
                #pragma unroll
                for (int j = 0; j < 8; j++)
                    acc[i][j] += ar[i] * br[j];
        }
    }

    #pragma unroll
    for (int i = 0; i < 8; i++) {
        const int r = row0 + ty * 4 + ((i < 4) ? i : (60 + i));   // ty*4+i or ty*4+64+(i-4)
        float4 lo = make_float4(acc[i][0], acc[i][1], acc[i][2], acc[i][3]);
        float4 hi = make_float4(acc[i][4], acc[i][5], acc[i][6], acc[i][7]);
        *reinterpret_cast<float4*>(&g_gates[dir][r][col0 + tx * 4])      = lo;
        *reinterpret_cast<float4*>(&g_gates[dir][r][col0 + tx * 4 + 64]) = hi;
    }
}

// ============================================================
// Char-level elementwise LSTM cell update (masked), float4
// ============================================================
__global__ void char_update(const int* __restrict__ lens,
                            const float* __restrict__ bif, const float* __restrict__ bhf,
                            const float* __restrict__ bib, const float* __restrict__ bhb,
                            int t)
{
    const int idx = blockIdx.x * blockDim.x + threadIdx.x;   // 2*NW*64 total
    const int k   = (idx & 63) * 4;
    const int w   = (idx >> 6) & (NW - 1);
    const int dir = idx >> 19;                // NW*64 = 2^19 per dir
    const float* __restrict__ bi = dir ? bib : bif;
    const float* __restrict__ bh = dir ? bhb : bhf;
    const int tt = dir ? (LC - 1 - t) : t;
    const bool m = tt < lens[w];

    const float* __restrict__ Gr = &g_gates[dir][w][0];
    const float4 i4 = *reinterpret_cast<const float4*>(&Gr[k]);
    const float4 f4 = *reinterpret_cast<const float4*>(&Gr[256 + k]);
    const float4 g4 = *reinterpret_cast<const float4*>(&Gr[512 + k]);
    const float4 o4 = *reinterpret_cast<const float4*>(&Gr[768 + k]);
    const float4 bii = *reinterpret_cast<const float4*>(&bi[k]);
    const float4 bhi = *reinterpret_cast<const float4*>(&bh[k]);
    const float4 bif4 = *reinterpret_cast<const float4*>(&bi[256 + k]);
    const float4 bhf4 = *reinterpret_cast<const float4*>(&bh[256 + k]);
    const float4 big4 = *reinterpret_cast<const float4*>(&bi[512 + k]);
    const float4 bhg4 = *reinterpret_cast<const float4*>(&bh[512 + k]);
    const float4 bio4 = *reinterpret_cast<const float4*>(&bi[768 + k]);
    const float4 bho4 = *reinterpret_cast<const float4*>(&bh[768 + k]);

    float4 hp = make_float4(0.f, 0.f, 0.f, 0.f);
    float4 cp = make_float4(0.f, 0.f, 0.f, 0.f);
    if (t > 0) {
        hp = *reinterpret_cast<const float4*>(&g_ch[dir][w][k]);
        cp = *reinterpret_cast<const float4*>(&g_cc[dir][w][k]);
    }

    float4 hn, cn;
    #define CELL(comp) { \
        const float ip = i4.comp + bii.comp + bhi.comp; \
        const float fp = f4.comp + bif4.comp + bhf4.comp; \
        const float gp = g4.comp + big4.comp + bhg4.comp; \
        const float op = o4.comp + bio4.comp + bho4.comp; \
        const float c_ = sigf(fp) * cp.comp + sigf(ip) * tanhf_(gp); \
        const float h_ = sigf(op) * tanhf_(c_); \
        cn.comp = m ? c_ : cp.comp; \
        hn.comp = m ? h_ : hp.comp; }
    CELL(x) CELL(y) CELL(z) CELL(w)
    #undef CELL

    *reinterpret_cast<float4*>(&g_ch[dir][w][k]) = hn;
    *reinterpret_cast<float4*>(&g_cc[dir][w][k]) = cn;
}

// ============================================================
// Word-level input-gate GEMM: wxg = [wemb | hT_f | hT_b] @ Wih^T + bih + bhh
// 128x128 tile, BK=8, 8x8 per thread.
// ============================================================
__global__ void __launch_bounds__(256, 2)
word_gemm(const float* __restrict__ wih_f, const float* __restrict__ wih_b,
          const float* __restrict__ bif,   const float* __restrict__ bhf,
          const float* __restrict__ bib,   const float* __restrict__ bhb,
          const int*   __restrict__ wseq,  const float* __restrict__ wemb)
{
    const int dir = blockIdx.z;
    const float* __restrict__ Wih = dir ? wih_b : wih_f;
    const float* __restrict__ bi  = dir ? bib   : bif;
    const float* __restrict__ bh  = dir ? bhb   : bhf;
    const int row0 = blockIdx.y * 128;
    const int col0 = blockIdx.x * 128;

    __shared__ float As[8][128];
    __shared__ float Bs[8][128];
    __shared__ int   sidx[128];

    const int tid = threadIdx.x;
    if (tid < 128) sidx[tid] = wseq[row0 + tid];

    const int tx = tid & 15;
    const int ty = tid >> 4;
    const int lrow = tid >> 1;
    const int lkq  = (tid & 1) * 4;

    float acc[8][8];
    #pragma unroll
    for (int i = 0; i < 8; i++)
        #pragma unroll
        for (int j = 0; j < 8; j++) acc[i][j] = 0.0f;

    __syncthreads();

    for (int kt = 0; kt < 102; kt++) {       // ceil(812/8)
        const int k = kt * 8 + lkq;          // quad base; segments split at mult of 4

        float4 av = make_float4(0.f, 0.f, 0.f, 0.f);
        float4 bv = make_float4(0.f, 0.f, 0.f, 0.f);
        if (k < WD)              av = *reinterpret_cast<const float4*>(&wemb[sidx[lrow] * WD + k]);
        else if (k < WD + HH)    av = *reinterpret_cast<const float4*>(&g_ch[0][row0 + lrow][k - WD]);
        else if (k < KW)         av = *reinterpret_cast<const float4*>(&g_ch[1][row0 + lrow][k - WD - HH]);
        if (k < KW)              bv = *reinterpret_cast<const float4*>(&Wih[(col0 + lrow) * KW + k]);

        __syncthreads();
        As[lkq + 0][lrow] = av.x; As[lkq + 1][lrow] = av.y;
        As[lkq + 2][lrow] = av.z; As[lkq + 3][lrow] = av.w;
        Bs[lkq + 0][lrow] = bv.x; Bs[lkq + 1][lrow] = bv.y;
        Bs[lkq + 2][lrow] = bv.z; Bs[lkq + 3][lrow] = bv.w;
        __syncthreads();

        #pragma unroll
        for (int kk = 0; kk < 8; kk++) {
            const float4 a0 = *reinterpret_cast<const float4*>(&As[kk][ty * 4]);
            const float4 a1 = *reinterpret_cast<const float4*>(&As[kk][ty * 4 + 64]);
            const float4 b0 = *reinterpret_cast<const float4*>(&Bs[kk][tx * 4]);
            const float4 b1 = *reinterpret_cast<const float4*>(&Bs[kk][tx * 4 + 64]);
            const float ar[8] = {a0.x, a0.y, a0.z, a0.w, a1.x, a1.y, a1.z, a1.w};
            const float br[8] = {b0.x, b0.y, b0.z, b0.w, b1.x, b1.y, b1.z, b1.w};
            #pragma unroll
            for (int i = 0; i < 8; i++)
                #pragma unroll
                for (int j = 0; j < 8; j++)
                    acc[i][j] += ar[i] * br[j];
        }
    }

    #pragma unroll
    for (int i = 0; i < 8; i++) {
        const int r = row0 + ty * 4 + ((i < 4) ? i : (60 + i));
        const int c0 = col0 + tx * 4;
        float4 lo = make_float4(acc[i][0] + bi[c0]     + bh[c0],
                                acc[i][1] + bi[c0 + 1] + bh[c0 + 1],
                                acc[i][2] + bi[c0 + 2] + bh[c0 + 2],
                                acc[i][3] + bi[c0 + 3] + bh[c0 + 3]);
        const int c1 = c0 + 64;
        float4 hi = make_float4(acc[i][4] + bi[c1]     + bh[c1],
                                acc[i][5] + bi[c1 + 1] + bh[c1 + 1],
                                acc[i][6] + bi[c1 + 2] + bh[c1 + 2],
                                acc[i][7] + bi[c1 + 3] + bh[c1 + 3]);
        *reinterpret_cast<float4*>(&g_wxg[dir][r][c0]) = lo;
        *reinterpret_cast<float4*>(&g_wxg[dir][r][c1]) = hi;
    }
}

// ============================================================
// Word-level sequential LSTM scan.
// One cluster of 8 CTAs per direction (grid = 16 CTAs, 2 clusters).
// Each CTA owns 32 h-dims (=128 gate rows); Whh slice in registers.
// Step sync: remote st.shared::cluster of h slices + remote
// mbarrier.arrive.release.cluster; local try_wait (parity).
// ============================================================
__global__ void __cluster_dims__(8, 1, 1) __launch_bounds__(256, 1)
word_scan(const float* __restrict__ whh_f, const float* __restrict__ whh_b)
{
    uint32_t rank;
    asm("mov.u32 %0, %%cluster_ctarank;" : "=r"(rank));
    const int dir = blockIdx.x >> 3;
    const float* __restrict__ Whh = dir ? whh_b : whh_f;

    const int tid  = threadIdx.x;
    const int lr   = tid >> 1;                // 0..127 local gate row
    const int half = tid & 1;                 // K half
    const int gg   = lr >> 5;                 // gate 0..3 (i,f,g,o)
    const int kl   = lr & 31;                 // h-dim within slice
    const int row_g = gg * 256 + (int)rank * 32 + kl;

    // Whh[row_g][half*128 .. +128) into registers
    float4 w4[32];
    const float4* wp = reinterpret_cast<const float4*>(&Whh[row_g * HH + half * 128]);
    #pragma unroll
    for (int i = 0; i < 32; i++) w4[i] = wp[i];

    __shared__ float    hbuf[2][256];
    __shared__ float    scratch[128];
    __shared__ uint64_t mbar[2];

    hbuf[0][tid] = 0.0f;
    if (tid == 0) {
        asm volatile("mbarrier.init.shared.b64 [%0], %1;" :: "r"(smem_u32(&mbar[0])), "r"(8) : "memory");
        asm volatile("mbarrier.init.shared.b64 [%0], %1;" :: "r"(smem_u32(&mbar[1])), "r"(8) : "memory");
    }
    __syncthreads();
    asm volatile("barrier.cluster.arrive.aligned;" ::: "memory");
    asm volatile("barrier.cluster.wait.aligned;"   ::: "memory");

    // Precompute remote addresses (stable across the loop)
    uint32_t st_addr[2][8];   // used by tid<32: &peer.hbuf[p][rank*32 + tid]
    if (tid < 32) {
        #pragma unroll
        for (int p = 0; p < 2; p++) {
            uint32_t laddr = smem_u32(&hbuf[p][rank * 32 + tid]);
            #pragma unroll
            for (int d = 0; d < 8; d++)
                asm("mapa.shared::cluster.u32 %0, %1, %2;"
                    : "=r"(st_addr[p][d]) : "r"(laddr), "r"(d));
        }
    }
    uint32_t arr_addr[2] = {0, 0};   // used by tid<8: &peer[tid].mbar[p]
    if (tid < 8) {
        #pragma unroll
        for (int p = 0; p < 2; p++)
            asm("mapa.shared::cluster.u32 %0, %1, %2;"
                : "=r"(arr_addr[p]) : "r"(smem_u32(&mbar[p])), "r"(tid));
    }

    float creg = 0.0f;       // cell state (valid for tid<32)
    int   ph[2] = {0, 0};    // parity per mbarrier

    for (int t = 0; t < NW; t++) {
        const int w = dir ? (NW - 1 - t) : t;
        const int p  = t & 1;
        const int np = p ^ 1;
        const float xgv = g_wxg[dir][w][row_g];   // LDG issued before the wait

        if (t > 0) {
            const uint32_t maddr = smem_u32(&mbar[p]);
            asm volatile(
                "{\n\t"
                ".reg .pred P;\n\t"
                "W_%=:\n\t"
                "mbarrier.try_wait.parity.acquire.cluster.shared::cta.b64 P, [%0], %1, 0x989680;\n\t"
                "@P bra.uni D_%=;\n\t"
                "bra.uni W_%=;\n\t"
                "D_%=:\n\t"
                "}"
                :: "r"(maddr), "r"(ph[p]) : "memory");
            ph[p] ^= 1;
        }

        // GEMV over this thread's 128-wide K half, 8 accumulator chains
        const float4* h4 = reinterpret_cast<const float4*>(&hbuf[p][half * 128]);
        float a0 = 0.f, a1 = 0.f, a2 = 0.f, a3 = 0.f;
        float a4 = 0.f, a5 = 0.f, a6 = 0.f, a7 = 0.f;
        #pragma unroll
        for (int i = 0; i < 32; i += 2) {
            const float4 hv0 = h4[i];
            const float4 hv1 = h4[i + 1];
            a0 += w4[i].x * hv0.x;     a1 += w4[i].y * hv0.y;
            a2 += w4[i].z * hv0.z;     a3 += w4[i].w * hv0.w;
            a4 += w4[i + 1].x * hv1.x; a5 += w4[i + 1].y * hv1.y;
            a6 += w4[i + 1].z * hv1.z; a7 += w4[i + 1].w * hv1.w;
        }
        float acc = ((a0 + a1) + (a2 + a3)) + ((a4 + a5) + (a6 + a7));
        acc += __shfl_xor_sync(0xffffffffu, acc, 1);
        if (half == 0) scratch[lr] = acc + xgv;
        __syncthreads();

        if (tid < 32) {
            const float ipre = scratch[tid];
            const float fpre = scratch[32 + tid];
            const float gpre = scratch[64 + tid];
            const float opre = scratch[96 + tid];
            const float cn = sigf(fpre) * creg + sigf(ipre) * tanhf_(gpre);
            const float hn = sigf(opre) * tanhf_(cn);
            creg = cn;
            g_hs[dir][w][rank * 32 + tid] = hn;
            #pragma unroll
            for (int d = 0; d < 8; d++)
                asm volatile("st.shared::cluster.f32 [%0], %1;"
                             :: "r"(st_addr[np][d]), "f"(hn) : "memory");
        }
        __syncthreads();   // order all 32 threads' remote stores before the arrives

        if (tid < 8)
            asm volatile("mbarrier.arrive.release.cluster.shared::cluster.b64 _, [%0];"
                         :: "r"(arr_addr[np]) : "memory");
    }
}

// ============================================================
// Classifier: logits + log_softmax for both heads
// ============================================================
__global__ void classifier(const float* __restrict__ Wp,  const float* __restrict__ bp,
                           const float* __restrict__ Wp2, const float* __restrict__ bp2,
                           float* __restrict__ out)
{
    const int w = blockIdx.x;
    __shared__ float4 row[HD / 4];
    __shared__ float  lg[T1 + T2];
    __shared__ float  red[2];

    const int tid = threadIdx.x;  // 128
    {
        const int i = tid * 4;
        float4 v;
        if (i < HH) v = *reinterpret_cast<const float4*>(&g_hs[0][w][i]);
        else        v = *reinterpret_cast<const float4*>(&g_hs[1][w][i - HH]);
        row[tid] = v;
    }
    __syncthreads();

    if (tid < T1 + T2) {
        const float4* Wr = (tid < T1)
            ? reinterpret_cast<const float4*>(&Wp[tid * HD])
            : reinterpret_cast<const float4*>(&Wp2[(tid - T1) * HD]);
        const float b = (tid < T1) ? bp[tid] : bp2[tid - T1];
        float a0 = 0.f, a1 = 0.f, a2 = 0.f, a3 = 0.f;
        #pragma unroll 4
        for (int k = 0; k < HD / 4; k += 4) {
            const float4 w0 = Wr[k],     r0 = row[k];
            const float4 w1 = Wr[k + 1], r1 = row[k + 1];
            const float4 w2 = Wr[k + 2], r2 = row[k + 2];
            const float4 w3 = Wr[k + 3], r3 = row[k + 3];
            a0 += w0.x * r0.x + w0.y * r0.y + w0.z * r0.z + w0.w * r0.w;
            a1 += w1.x * r1.x + w1.y * r1.y + w1.z * r1.z + w1.w * r1.w;
            a2 += w2.x * r2.x + w2.y * r2.y + w2.z * r2.z + w2.w * r2.w;
            a3 += w3.x * r3.x + w3.y * r3.y + w3.z * r3.z + w3.w * r3.w;
        }
        lg[tid] = (a0 + a1) + (a2 + a3) + b;
    }
    __syncthreads();

    if (tid < 2) {
        const int base = tid ? T1 : 0;
        const int n    = tid ? T2 : T1;
        float mx = -1e30f;
        for (int j = 0; j < n; j++) mx = fmaxf(mx, lg[base + j]);
        float s = 0.0f;
        for (int j = 0; j < n; j++) s += expf(lg[base + j] - mx);
        red[tid] = mx + logf(s);
    }
    __syncthreads();

    if (tid < T1)            out[w * T1 + tid] = lg[tid] - red[0];
    else if (tid < T1 + T2)  out[NW * T1 + w * T2 + (tid - T1)] = lg[tid] - red[1];
}

// ============================================================
// Launch
// ============================================================
extern "C" void kernel_launch(void* const* d_in, const int* in_sizes, int n_in,
                              void* d_out, int out_size)
{
    (void)in_sizes; (void)n_in; (void)out_size;
    const int*   wseq  = (const int*)d_in[0];
    const int*   cseq  = (const int*)d_in[1];
    const int*   lens  = (const int*)d_in[2];
    const float* cemb  = (const float*)d_in[3];
    const float* wemb  = (const float*)d_in[4];
    const float* cfWih = (const float*)d_in[5];
    const float* cfWhh = (const float*)d_in[6];
    const float* cfbi  = (const float*)d_in[7];
    const float* cfbh  = (const float*)d_in[8];
    const float* cbWih = (const float*)d_in[9];
    const float* cbWhh = (const float*)d_in[10];
    const float* cbbi  = (const float*)d_in[11];
    const float* cbbh  = (const float*)d_in[12];
    const float* wfWih = (const float*)d_in[13];
    const float* wfWhh = (const float*)d_in[14];
    const float* wfbi  = (const float*)d_in[15];
    const float* wfbh  = (const float*)d_in[16];
    const float* wbWih = (const float*)d_in[17];
    const float* wbWhh = (const float*)d_in[18];
    const float* wbbi  = (const float*)d_in[19];
    const float* wbbh  = (const float*)d_in[20];
    const float* Wp    = (const float*)d_in[21];
    const float* bp    = (const float*)d_in[22];
    const float* Wp2   = (const float*)d_in[23];
    const float* bp2   = (const float*)d_in[24];
    float* out = (float*)d_out;

    const dim3 gg(G4 / 128, NW / 128, 2);   // 8 x 64 x 2

    for (int t = 0; t < LC; t++) {
        char_gemm<<<gg, 256>>>(cfWhh, cfWih, cbWhh, cbWih, cseq, cemb, t);
        char_update<<<(2 * NW * 64) / 256, 256>>>(lens, cfbi, cfbh, cbbi, cbbh, t);
    }
    word_gemm<<<gg, 256>>>(wfWih, wbWih, wfbi, wfbh, wbbi, wbbh, wseq, wemb);
    word_scan<<<16, 256>>>(wfWhh, wbWhh);
    classifier<<<NW, 128>>>(Wp, bp, Wp2, bp2, out);
}

// round 4
// speedup vs baseline: 1.1903x; 1.1903x over previous
#include <cuda_runtime.h>
#include <math.h>
#include <stdint.h>

#define NW 8192
#define LC 16
#define CD 100
#define WD 300
#define HD 512
#define HH 256
#define G4 1024
#define T1 48
#define T2 32
#define KC (HH + CD)   // 356
#define KW (WD + HD)   // 812

typedef unsigned long long u64;

// ---- scratch (device globals; no allocation allowed) ----
__device__ float g_gates[2][NW][G4];   // char gate preacts (per step, no bias)
__device__ float g_ch[2][NW][HH];      // char h (becomes char_feat)
__device__ float g_cc[2][NW][HH];      // char c
__device__ float g_wxg[2][NW][G4];     // word-level input gates (+biases)
__device__ float g_hs[2][NW][HH];      // word-level hidden states per step

// ---- f32x2 packed-math helpers (sm_100+) ----
__device__ __forceinline__ u64 dup2(float v) {
    u64 r; asm("mov.b64 %0, {%1, %1};" : "=l"(r) : "f"(v)); return r;
}
__device__ __forceinline__ void fma2(u64& d, u64 a, u64 b) {
    asm("fma.rn.f32x2 %0, %1, %2, %0;" : "+l"(d) : "l"(a), "l"(b));
}
__device__ __forceinline__ float2 unpack2(u64 v) {
    float2 r; asm("mov.b64 {%0, %1}, %2;" : "=f"(r.x), "=f"(r.y) : "l"(v)); return r;
}
__device__ __forceinline__ float tanha(float x) {
    float r; asm("tanh.approx.f32 %0, %1;" : "=f"(r) : "f"(x)); return r;
}
__device__ __forceinline__ float siga(float x) {   // sigmoid via tanh: (1+tanh(x/2))/2
    return fmaf(tanha(0.5f * x), 0.5f, 0.5f);
}
__device__ __forceinline__ uint32_t smem_u32(const void* p) {
    return (uint32_t)__cvta_generic_to_shared(p);
}

// ============================================================
// Char-level step GEMM: gates[dir][w][n] = sum_k A[w,k]*B[n,k]
// A = [h(256) | char_emb(100)], B = [Whh | Wih] (both K-major rows)
// 128x128 tile, BK=8, 256 threads, 8x8 per thread, f32x2 FMA,
// register-prefetch of next K-tile.
// ============================================================
__global__ void __launch_bounds__(256, 2)
char_gemm(const float* __restrict__ whh_f, const float* __restrict__ wih_f,
          const float* __restrict__ whh_b, const float* __restrict__ wih_b,
          const int*   __restrict__ cseq,  const float* __restrict__ cemb,
          int t)
{
    const int dir = blockIdx.z;
    const float* __restrict__ Whh = dir ? whh_b : whh_f;
    const float* __restrict__ Wih = dir ? wih_b : wih_f;
    const int tt   = dir ? (LC - 1 - t) : t;
    const int row0 = blockIdx.y * 128;
    const int col0 = blockIdx.x * 128;

    __shared__ float As[8][128];
    __shared__ float Bs[8][128];
    __shared__ int   sidx[128];

    const int tid = threadIdx.x;
    if (tid < 128) sidx[tid] = cseq[(row0 + tid) * LC + tt];

    const int tx = tid & 15;          // 0..15 -> col groups
    const int ty = tid >> 4;          // 0..15 -> row groups
    const int lrow = tid >> 1;        // 0..127 (load row)
    const int lkq  = (tid & 1) * 4;   // 0 or 4 (load k quad)

    u64 acc2[8][4];
    #pragma unroll
    for (int i = 0; i < 8; i++)
        #pragma unroll
        for (int j = 0; j < 4; j++) acc2[i][j] = 0ull;

    const int kt0 = (t == 0) ? 32 : 0;   // at t=0, h==0 -> skip K[0,256)
    __syncthreads();                     // sidx ready

    #define CLOAD(KT, AV, BV) { \
        const int k_ = (KT) * 8 + lkq; \
        AV = make_float4(0.f, 0.f, 0.f, 0.f); \
        BV = make_float4(0.f, 0.f, 0.f, 0.f); \
        if (k_ < HH) { \
            AV = *reinterpret_cast<const float4*>(&g_ch[dir][row0 + lrow][k_]); \
            BV = *reinterpret_cast<const float4*>(&Whh[(col0 + lrow) * HH + k_]); \
        } else if (k_ < KC) { \
            AV = *reinterpret_cast<const float4*>(&cemb[sidx[lrow] * CD + (k_ - HH)]); \
            BV = *reinterpret_cast<const float4*>(&Wih[(col0 + lrow) * CD + (k_ - HH)]); \
        } }

    float4 av, bv;
    CLOAD(kt0, av, bv);

    for (int kt = kt0; kt < 45; kt++) {
        As[lkq + 0][lrow] = av.x; As[lkq + 1][lrow] = av.y;
        As[lkq + 2][lrow] = av.z; As[lkq + 3][lrow] = av.w;
        Bs[lkq + 0][lrow] = bv.x; Bs[lkq + 1][lrow] = bv.y;
        Bs[lkq + 2][lrow] = bv.z; Bs[lkq + 3][lrow] = bv.w;
        __syncthreads();   // tile ready

        // prefetch next K-tile into registers (latency hidden by compute)
        if (kt + 1 < 45) { CLOAD(kt + 1, av, bv); }

        #pragma unroll
        for (int kk = 0; kk < 8; kk++) {
            const float4 a0 = *reinterpret_cast<const float4*>(&As[kk][ty * 4]);
            const float4 a1 = *reinterpret_cast<const float4*>(&As[kk][ty * 4 + 64]);
            const ulonglong2 b0 = *reinterpret_cast<const ulonglong2*>(&Bs[kk][tx * 4]);
            const ulonglong2 b1 = *reinterpret_cast<const ulonglong2*>(&Bs[kk][tx * 4 + 64]);
            u64 ad[8] = {dup2(a0.x), dup2(a0.y), dup2(a0.z), dup2(a0.w),
                         dup2(a1.x), dup2(a1.y), dup2(a1.z), dup2(a1.w)};
            const u64 bb[4] = {b0.x, b0.y, b1.x, b1.y};
            #pragma unroll
            for (int i = 0; i < 8; i++)
                #pragma unroll
                for (int j = 0; j < 4; j++)
                    fma2(acc2[i][j], ad[i], bb[j]);
        }
        __syncthreads();   // tile fully consumed before next store
    }
    #undef CLOAD

    #pragma unroll
    for (int i = 0; i < 8; i++) {
        const int r = row0 + ty * 4 + ((i < 4) ? i : (60 + i));
        const float2 p0 = unpack2(acc2[i][0]);
        const float2 p1 = unpack2(acc2[i][1]);
        const float2 p2 = unpack2(acc2[i][2]);
        const float2 p3 = unpack2(acc2[i][3]);
        *reinterpret_cast<float4*>(&g_gates[dir][r][col0 + tx * 4])      = make_float4(p0.x, p0.y, p1.x, p1.y);
        *reinterpret_cast<float4*>(&g_gates[dir][r][col0 + tx * 4 + 64]) = make_float4(p2.x, p2.y, p3.x, p3.y);
    }
}

// ============================================================
// Char-level elementwise LSTM cell update (masked), float4, tanh.approx
// ============================================================
__global__ void char_update(const int* __restrict__ lens,
                            const float* __restrict__ bif, const float* __restrict__ bhf,
                            const float* __restrict__ bib, const float* __restrict__ bhb,
                            int t)
{
    const int idx = blockIdx.x * blockDim.x + threadIdx.x;   // 2*NW*64 total
    const int k   = (idx & 63) * 4;
    const int w   = (idx >> 6) & (NW - 1);
    const int dir = idx >> 19;                // NW*64 = 2^19 per dir
    const float* __restrict__ bi = dir ? bib : bif;
    const float* __restrict__ bh = dir ? bhb : bhf;
    const int tt = dir ? (LC - 1 - t) : t;
    const bool m = tt < lens[w];

    const float* __restrict__ Gr = &g_gates[dir][w][0];
    const float4 i4 = *reinterpret_cast<const float4*>(&Gr[k]);
    const float4 f4 = *reinterpret_cast<const float4*>(&Gr[256 + k]);
    const float4 g4 = *reinterpret_cast<const float4*>(&Gr[512 + k]);
    const float4 o4 = *reinterpret_cast<const float4*>(&Gr[768 + k]);
    const float4 bii = *reinterpret_cast<const float4*>(&bi[k]);
    const float4 bhi = *reinterpret_cast<const float4*>(&bh[k]);
    const float4 bif4 = *reinterpret_cast<const float4*>(&bi[256 + k]);
    const float4 bhf4 = *reinterpret_cast<const float4*>(&bh[256 + k]);
    const float4 big4 = *reinterpret_cast<const float4*>(&bi[512 + k]);
    const float4 bhg4 = *reinterpret_cast<const float4*>(&bh[512 + k]);
    const float4 bio4 = *reinterpret_cast<const float4*>(&bi[768 + k]);
    const float4 bho4 = *reinterpret_cast<const float4*>(&bh[768 + k]);

    float4 hp = make_float4(0.f, 0.f, 0.f, 0.f);
    float4 cp = make_float4(0.f, 0.f, 0.f, 0.f);
    if (t > 0) {
        hp = *reinterpret_cast<const float4*>(&g_ch[dir][w][k]);
        cp = *reinterpret_cast<const float4*>(&g_cc[dir][w][k]);
    }

    float4 hn, cn;
    #define CELL(comp) { \
        const float ip = i4.comp + bii.comp + bhi.comp; \
        const float fp = f4.comp + bif4.comp + bhf4.comp; \
        const float gp = g4.comp + big4.comp + bhg4.comp; \
        const float op = o4.comp + bio4.comp + bho4.comp; \
        const float c_ = siga(fp) * cp.comp + siga(ip) * tanha(gp); \
        const float h_ = siga(op) * tanha(c_); \
        cn.comp = m ? c_ : cp.comp; \
        hn.comp = m ? h_ : hp.comp; }
    CELL(x) CELL(y) CELL(z) CELL(w)
    #undef CELL

    *reinterpret_cast<float4*>(&g_ch[dir][w][k]) = hn;
    *reinterpret_cast<float4*>(&g_cc[dir][w][k]) = cn;
}

// ============================================================
// Word-level input-gate GEMM: wxg = [wemb | hT_f | hT_b] @ Wih^T + bih + bhh
// 128x128 tile, BK=8, 8x8 per thread, f32x2 + register prefetch.
// ============================================================
__global__ void __launch_bounds__(256, 2)
word_gemm(const float* __restrict__ wih_f, const float* __restrict__ wih_b,
          const float* __restrict__ bif,   const float* __restrict__ bhf,
          const float* __restrict__ bib,   const float* __restrict__ bhb,
          const int*   __restrict__ wseq,  const float* __restrict__ wemb)
{
    const int dir = blockIdx.z;
    const float* __restrict__ Wih = dir ? wih_b : wih_f;
    const float* __restrict__ bi  = dir ? bib   : bif;
    const float* __restrict__ bh  = dir ? bhb   : bhf;
    const int row0 = blockIdx.y * 128;
    const int col0 = blockIdx.x * 128;

    __shared__ float As[8][128];
    __shared__ float Bs[8][128];
    __shared__ int   sidx[128];

    const int tid = threadIdx.x;
    if (tid < 128) sidx[tid] = wseq[row0 + tid];

    const int tx = tid & 15;
    const int ty = tid >> 4;
    const int lrow = tid >> 1;
    const int lkq  = (tid & 1) * 4;

    u64 acc2[8][4];
    #pragma unroll
    for (int i = 0; i < 8; i++)
        #pragma unroll
        for (int j = 0; j < 4; j++) acc2[i][j] = 0ull;

    __syncthreads();   // sidx ready

    #define WLOAD(KT, AV, BV) { \
        const int k_ = (KT) * 8 + lkq; \
        AV = make_float4(0.f, 0.f, 0.f, 0.f); \
        BV = make_float4(0.f, 0.f, 0.f, 0.f); \
        if (k_ < WD)             AV = *reinterpret_cast<const float4*>(&wemb[sidx[lrow] * WD + k_]); \
        else if (k_ < WD + HH)   AV = *reinterpret_cast<const float4*>(&g_ch[0][row0 + lrow][k_ - WD]); \
        else if (k_ < KW)        AV = *reinterpret_cast<const float4*>(&g_ch[1][row0 + lrow][k_ - WD - HH]); \
        if (k_ < KW)             BV = *reinterpret_cast<const float4*>(&Wih[(col0 + lrow) * KW + k_]); }

    float4 av, bv;
    WLOAD(0, av, bv);

    for (int kt = 0; kt < 102; kt++) {       // ceil(812/8)
        As[lkq + 0][lrow] = av.x; As[lkq + 1][lrow] = av.y;
        As[lkq + 2][lrow] = av.z; As[lkq + 3][lrow] = av.w;
        Bs[lkq + 0][lrow] = bv.x; Bs[lkq + 1][lrow] = bv.y;
        Bs[lkq + 2][lrow] = bv.z; Bs[lkq + 3][lrow] = bv.w;
        __syncthreads();

        if (kt + 1 < 102) { WLOAD(kt + 1, av, bv); }

        #pragma unroll
        for (int kk = 0; kk < 8; kk++) {
            const float4 a0 = *reinterpret_cast<const float4*>(&As[kk][ty * 4]);
            const float4 a1 = *reinterpret_cast<const float4*>(&As[kk][ty * 4 + 64]);
            const ulonglong2 b0 = *reinterpret_cast<const ulonglong2*>(&Bs[kk][tx * 4]);
            const ulonglong2 b1 = *reinterpret_cast<const ulonglong2*>(&Bs[kk][tx * 4 + 64]);
            u64 ad[8] = {dup2(a0.x), dup2(a0.y), dup2(a0.z), dup2(a0.w),
                         dup2(a1.x), dup2(a1.y), dup2(a1.z), dup2(a1.w)};
            const u64 bb[4] = {b0.x, b0.y, b1.x, b1.y};
            #pragma unroll
            for (int i = 0; i < 8; i++)
                #pragma unroll
                for (int j = 0; j < 4; j++)
                    fma2(acc2[i][j], ad[i], bb[j]);
        }
        __syncthreads();
    }
    #undef WLOAD

    #pragma unroll
    for (int i = 0; i < 8; i++) {
        const int r = row0 + ty * 4 + ((i < 4) ? i : (60 + i));
        const int c0 = col0 + tx * 4;
        const int c1 = c0 + 64;
        const float2 p0 = unpack2(acc2[i][0]);
        const float2 p1 = unpack2(acc2[i][1]);
        const float2 p2 = unpack2(acc2[i][2]);
        const float2 p3 = unpack2(acc2[i][3]);
        *reinterpret_cast<float4*>(&g_wxg[dir][r][c0]) =
            make_float4(p0.x + bi[c0]     + bh[c0],
                        p0.y + bi[c0 + 1] + bh[c0 + 1],
                        p1.x + bi[c0 + 2] + bh[c0 + 2],
                        p1.y + bi[c0 + 3] + bh[c0 + 3]);
        *reinterpret_cast<float4*>(&g_wxg[dir][r][c1]) =
            make_float4(p2.x + bi[c1]     + bh[c1],
                        p2.y + bi[c1 + 1] + bh[c1 + 1],
                        p3.x + bi[c1 + 2] + bh[c1 + 2],
                        p3.y + bi[c1 + 3] + bh[c1 + 3]);
    }
}

// ============================================================
// Word-level sequential LSTM scan.
// One cluster of 8 CTAs per direction (grid = 16 CTAs, 2 clusters).
// Each CTA owns 32 h-dims (=128 gate rows); Whh slice in registers.
// f32x2 GEMV; tanh.approx cell; double-buffered scratch; one
// __syncthreads per step. Sync: remote st.shared::cluster + remote
// mbarrier.arrive.release.cluster; local try_wait (parity).
// ============================================================
__global__ void __cluster_dims__(8, 1, 1) __launch_bounds__(256, 1)
word_scan(const float* __restrict__ whh_f, const float* __restrict__ whh_b)
{
    uint32_t rank;
    asm("mov.u32 %0, %%cluster_ctarank;" : "=r"(rank));
    const int dir = blockIdx.x >> 3;
    const float* __restrict__ Whh = dir ? whh_b : whh_f;

    const int tid  = threadIdx.x;
    const int lr   = tid >> 1;                // 0..127 local gate row
    const int half = tid & 1;                 // K half
    const int gg   = lr >> 5;                 // gate 0..3 (i,f,g,o)
    const int kl   = lr & 31;                 // h-dim within slice
    const int row_g = gg * 256 + (int)rank * 32 + kl;

    // Whh[row_g][half*128 .. +128) into registers as packed pairs
    ulonglong2 wl[32];
    const ulonglong2* wp = reinterpret_cast<const ulonglong2*>(&Whh[row_g * HH + half * 128]);
    #pragma unroll
    for (int i = 0; i < 32; i++) wl[i] = wp[i];

    __shared__ float    hbuf[2][256];
    __shared__ float    scratch[2][128];
    __shared__ uint64_t mbar[2];

    hbuf[0][tid] = 0.0f;
    if (tid == 0) {
        asm volatile("mbarrier.init.shared.b64 [%0], %1;" :: "r"(smem_u32(&mbar[0])), "r"(8) : "memory");
        asm volatile("mbarrier.init.shared.b64 [%0], %1;" :: "r"(smem_u32(&mbar[1])), "r"(8) : "memory");
    }
    __syncthreads();
    asm volatile("barrier.cluster.arrive.aligned;" ::: "memory");
    asm volatile("barrier.cluster.wait.aligned;"   ::: "memory");

    // Precompute remote addresses (stable across the loop)
    uint32_t st_addr[2][8];   // used by tid<32: &peer.hbuf[p][rank*32 + tid]
    if (tid < 32) {
        #pragma unroll
        for (int p = 0; p < 2; p++) {
            uint32_t laddr = smem_u32(&hbuf[p][rank * 32 + tid]);
            #pragma unroll
            for (int d = 0; d < 8; d++)
                asm("mapa.shared::cluster.u32 %0, %1, %2;"
                    : "=r"(st_addr[p][d]) : "r"(laddr), "r"(d));
        }
    }
    uint32_t arr_addr[2] = {0, 0};   // used by tid<8: &peer[tid].mbar[p]
    if (tid < 8) {
        #pragma unroll
        for (int p = 0; p < 2; p++)
            asm("mapa.shared::cluster.u32 %0, %1, %2;"
                : "=r"(arr_addr[p]) : "r"(smem_u32(&mbar[p])), "r"(tid));
    }

    float creg = 0.0f;       // cell state (valid for tid<32)
    int   ph[2] = {0, 0};    // parity per mbarrier

    for (int t = 0; t < NW; t++) {
        const int w = dir ? (NW - 1 - t) : t;
        const int p  = t & 1;
        const int np = p ^ 1;
        const float xgv = __ldcs(&g_wxg[dir][w][row_g]);   // LDG issued before the wait

        if (t > 0) {
            const uint32_t maddr = smem_u32(&mbar[p]);
            asm volatile(
                "{\n\t"
                ".reg .pred P;\n\t"
                "W_%=:\n\t"
                "mbarrier.try_wait.parity.acquire.cluster.shared::cta.b64 P, [%0], %1, 0x989680;\n\t"
                "@P bra.uni D_%=;\n\t"
                "bra.uni W_%=;\n\t"
                "D_%=:\n\t"
                "}"
                :: "r"(maddr), "r"(ph[p]) : "memory");
            ph[p] ^= 1;
        }

        // GEMV over this thread's 128-wide K half, f32x2, 8 chains
        const ulonglong2* h2 = reinterpret_cast<const ulonglong2*>(&hbuf[p][half * 128]);
        u64 a0 = 0ull, a1 = 0ull, a2 = 0ull, a3 = 0ull;
        u64 a4 = 0ull, a5 = 0ull, a6 = 0ull, a7 = 0ull;
        #pragma unroll
        for (int i = 0; i < 32; i += 4) {
            const ulonglong2 h0 = h2[i],      h1 = h2[i + 1];
            const ulonglong2 hh2 = h2[i + 2], h3 = h2[i + 3];
            fma2(a0, wl[i].x,     h0.x);  fma2(a1, wl[i].y,     h0.y);
            fma2(a2, wl[i + 1].x, h1.x);  fma2(a3, wl[i + 1].y, h1.y);
            fma2(a4, wl[i + 2].x, hh2.x); fma2(a5, wl[i + 2].y, hh2.y);
            fma2(a6, wl[i + 3].x, h3.x);  fma2(a7, wl[i + 3].y, h3.y);
        }
        const float2 s0 = unpack2(a0), s1 = unpack2(a1), s2 = unpack2(a2), s3 = unpack2(a3);
        const float2 s4 = unpack2(a4), s5 = unpack2(a5), s6 = unpack2(a6), s7 = unpack2(a7);
        float acc = (((s0.x + s0.y) + (s1.x + s1.y)) + ((s2.x + s2.y) + (s3.x + s3.y)))
                  + (((s4.x + s4.y) + (s5.x + s5.y)) + ((s6.x + s6.y) + (s7.x + s7.y)));
        acc += __shfl_xor_sync(0xffffffffu, acc, 1);
        if (half == 0) scratch[p][lr] = acc + xgv;
        __syncthreads();                    // scratch[p] visible to warp 0

        if (tid < 32) {
            const float ipre = scratch[p][tid];
            const float fpre = scratch[p][32 + tid];
            const float gpre = scratch[p][64 + tid];
            const float opre = scratch[p][96 + tid];
            const float cn = siga(fpre) * creg + siga(ipre) * tanha(gpre);
            const float hn = siga(opre) * tanha(cn);
            creg = cn;
            g_hs[dir][w][rank * 32 + tid] = hn;
            #pragma unroll
            for (int d = 0; d < 8; d++)
                asm volatile("st.shared::cluster.f32 [%0], %1;"
                             :: "r"(st_addr[np][d]), "f"(hn) : "memory");
            __syncwarp();                   // order warp-0 stores before arrives
            if (tid < 8)
                asm volatile("mbarrier.arrive.release.cluster.shared::cluster.b64 _, [%0];"
                             :: "r"(arr_addr[np]) : "memory");
        }
        // warps 1..7 proceed directly to step t+1 (gated by mbar[np]);
        // scratch double-buffering removes the WAR hazard.
    }
}

// ============================================================
// Classifier: logits + log_softmax for both heads (f32x2 dot)
// ============================================================
__global__ void classifier(const float* __restrict__ Wp,  const float* __restrict__ bp,
                           const float* __restrict__ Wp2, const float* __restrict__ bp2,
                           float* __restrict__ out)
{
    const int w = blockIdx.x;
    __shared__ float4 row[HD / 4];
    __shared__ float  lg[T1 + T2];
    __shared__ float  red[2];

    const int tid = threadIdx.x;  // 128
    {
        const int i = tid * 4;
        float4 v;
        if (i < HH) v = *reinterpret_cast<const float4*>(&g_hs[0][w][i]);
        else        v = *reinterpret_cast<const float4*>(&g_hs[1][w][i - HH]);
        row[tid] = v;
    }
    __syncthreads();

    if (tid < T1 + T2) {
        const ulonglong2* W2 = (tid < T1)
            ? reinterpret_cast<const ulonglong2*>(&Wp[tid * HD])
            : reinterpret_cast<const ulonglong2*>(&Wp2[(tid - T1) * HD]);
        const ulonglong2* R2 = reinterpret_cast<const ulonglong2*>(row);
        const float b = (tid < T1) ? bp[tid] : bp2[tid - T1];
        u64 c0 = 0ull, c1 = 0ull, c2 = 0ull, c3 = 0ull;
        #pragma unroll 8
        for (int k = 0; k < HD / 4; k += 2) {     // 128 ulonglong2 entries
            const ulonglong2 w0 = W2[k],     r0 = R2[k];
            const ulonglong2 w1 = W2[k + 1], r1 = R2[k + 1];
            fma2(c0, w0.x, r0.x); fma2(c1, w0.y, r0.y);
            fma2(c2, w1.x, r1.x); fma2(c3, w1.y, r1.y);
        }
        const float2 u0 = unpack2(c0), u1 = unpack2(c1), u2 = unpack2(c2), u3 = unpack2(c3);
        lg[tid] = ((u0.x + u0.y) + (u1.x + u1.y)) + ((u2.x + u2.y) + (u3.x + u3.y)) + b;
    }
    __syncthreads();

    if (tid < 2) {
        const int base = tid ? T1 : 0;
        const int n    = tid ? T2 : T1;
        float mx = -1e30f;
        for (int j = 0; j < n; j++) mx = fmaxf(mx, lg[base + j]);
        float s = 0.0f;
        for (int j = 0; j < n; j++) s += expf(lg[base + j] - mx);
        red[tid] = mx + logf(s);
    }
    __syncthreads();

    if (tid < T1)            out[w * T1 + tid] = lg[tid] - red[0];
    else if (tid < T1 + T2)  out[NW * T1 + w * T2 + (tid - T1)] = lg[tid] - red[1];
}

// ============================================================
// Launch
// ============================================================
extern "C" void kernel_launch(void* const* d_in, const int* in_sizes, int n_in,
                              void* d_out, int out_size)
{
    (void)in_sizes; (void)n_in; (void)out_size;
    const int*   wseq  = (const int*)d_in[0];
    const int*   cseq  = (const int*)d_in[1];
    const int*   lens  = (const int*)d_in[2];
    const float* cemb  = (const float*)d_in[3];
    const float* wemb  = (const float*)d_in[4];
    const float* cfWih = (const float*)d_in[5];
    const float* cfWhh = (const float*)d_in[6];
    const float* cfbi  = (const float*)d_in[7];
    const float* cfbh  = (const float*)d_in[8];
    const float* cbWih = (const float*)d_in[9];
    const float* cbWhh = (const float*)d_in[10];
    const float* cbbi  = (const float*)d_in[11];
    const float* cbbh  = (const float*)d_in[12];
    const float* wfWih = (const float*)d_in[13];
    const float* wfWhh = (const float*)d_in[14];
    const float* wfbi  = (const float*)d_in[15];
    const float* wfbh  = (const float*)d_in[16];
    const float* wbWih = (const float*)d_in[17];
    const float* wbWhh = (const float*)d_in[18];
    const float* wbbi  = (const float*)d_in[19];
    const float* wbbh  = (const float*)d_in[20];
    const float* Wp    = (const float*)d_in[21];
    const float* bp    = (const float*)d_in[22];
    const float* Wp2   = (const float*)d_in[23];
    const float* bp2   = (const float*)d_in[24];
    float* out = (float*)d_out;

    const dim3 gg(G4 / 128, NW / 128, 2);   // 8 x 64 x 2

    for (int t = 0; t < LC; t++) {
        char_gemm<<<gg, 256>>>(cfWhh, cfWih, cbWhh, cbWih, cseq, cemb, t);
        char_update<<<(2 * NW * 64) / 256, 256>>>(lens, cfbi, cfbh, cbbi, cbbh, t);
    }
    word_gemm<<<gg, 256>>>(wfWih, wbWih, wfbi, wfbh, wbbi, wbbh, wseq, wemb);
    word_scan<<<16, 256>>>(wfWhh, wbWhh);
    classifier<<<NW, 128>>>(Wp, bp, Wp2, bp2, out);
}